// round 7
// baseline (speedup 1.0000x reference)
#include <cuda_runtime.h>
#include <cstdint>

// ---------------------------------------------------------------------------
// BaseGCN fused: kNN + Laplacian. One CTA = 4 rows, 256 threads, 4096 CTAs.
// out[g,i,j] = (j==i) - (1/k) * [j in knn(i)]   (deg == k always).
//
//  stage: SoA float4 arrays xs4/ys4/zs4 (16KB each) -> conflict-free LDS.128
//         (4 wavefronts each, vs 6 per LDS.64 at the old 24B stride)
//  zero:  CTA zeroes its 4 output rows early (__stcs, drains under compute)
//  pass1: 4 candidates/iter; ulonglong2 LDS.128 gives packed f32x2 operands
//         directly; per-thread minima for 4 rows -> 32 group-of-8 minima
//  thr:   warp r<4 counting-ranks the 32 minima; rank k-1 value T guarantees
//         >= k candidates <= T  =>  collected set contains the exact top-k
//  collect: recompute, FMIN-tree + single gate compare, vote, ~23 cands
//  pass4: warps w / w+4 co-rank row (w&3) -> exact top-k (64-bit
//         (ord(dist), idx) keys => lowest-index ties, == lax.top_k)
//  scatter: warp r<4 writes ~k nonzeros + diagonal of its row
// ---------------------------------------------------------------------------

constexpr int NN   = 4096;
constexpr int ROWS = 4;
constexpr int NT   = 256;
constexpr int CAP  = 64;

// smem offsets (bytes)
constexpr int OFF_X    = 0;          // float4 xs4[1024]   16384
constexpr int OFF_Y    = 16384;      // float4 ys4[1024]   16384
constexpr int OFF_Z    = 32768;      // float4 zs4[1024]   16384
constexpr int OFF_TM   = 49152;      // u16 tm16[4][32]      256
constexpr int OFF_CAND = 49408;      // u64 cand[4][64]     2048
constexpr int OFF_KNN  = 51456;      // int knn[4][32]       512
constexpr int OFF_MISC = 51968;      // sT16[4] cnt[4] act[4] anyf
constexpr int SMEM_TOTAL = OFF_MISC + 128;   // 52096 -> 4 CTAs/SM

using u64 = unsigned long long;

__device__ __forceinline__ u64 fma2(u64 a, u64 b, u64 c) {
    u64 d; asm("fma.rn.f32x2 %0, %1, %2, %3;" : "=l"(d) : "l"(a), "l"(b), "l"(c));
    return d;
}
__device__ __forceinline__ u64 mul2(u64 a, u64 b) {
    u64 d; asm("mul.rn.f32x2 %0, %1, %2;" : "=l"(d) : "l"(a), "l"(b));
    return d;
}
__device__ __forceinline__ u64 pack2(float a, float b) {
    u64 d; asm("mov.b64 %0, {%1, %2};" : "=l"(d) : "f"(a), "f"(b));
    return d;
}
__device__ __forceinline__ u64 splat2(float a) { return pack2(a, a); }
__device__ __forceinline__ float lo2(u64 v) { return __uint_as_float((unsigned)v); }
__device__ __forceinline__ float hi2(u64 v) { return __uint_as_float((unsigned)(v >> 32)); }

__device__ __forceinline__ unsigned f2ord(float f) {
    unsigned b = __float_as_uint(f);
    return b ^ ((b & 0x80000000u) ? 0xFFFFFFFFu : 0x80000000u);
}
__device__ __forceinline__ float ord2f(unsigned u) {
    unsigned b = (u & 0x80000000u) ? (u ^ 0x80000000u) : ~u;
    return __uint_as_float(b);
}

extern "C" __global__ void __launch_bounds__(NT, 4)
gcn_fused(const float* __restrict__ x, const int* __restrict__ kptr,
          float* __restrict__ out) {
    extern __shared__ unsigned char sm[];
    float4* xs4 = reinterpret_cast<float4*>(sm + OFF_X);
    float4* ys4 = reinterpret_cast<float4*>(sm + OFF_Y);
    float4* zs4 = reinterpret_cast<float4*>(sm + OFF_Z);
    const ulonglong2* xsu = reinterpret_cast<const ulonglong2*>(sm + OFF_X);
    const ulonglong2* ysu = reinterpret_cast<const ulonglong2*>(sm + OFF_Y);
    const ulonglong2* zsu = reinterpret_cast<const ulonglong2*>(sm + OFF_Z);
    unsigned short (*tm16)[32] =
        reinterpret_cast<unsigned short(*)[32]>(sm + OFF_TM);
    u64 (*cand)[CAP] = reinterpret_cast<u64(*)[CAP]>(sm + OFF_CAND);
    int (*knn)[32]   = reinterpret_cast<int(*)[32]>(sm + OFF_KNN);
    unsigned* sT16 = reinterpret_cast<unsigned*>(sm + OFF_MISC);
    int*      cnt  = reinterpret_cast<int*>(sm + OFF_MISC + 16);
    int*      act  = reinterpret_cast<int*>(sm + OFF_MISC + 32);
    int*      anyf = reinterpret_cast<int*>(sm + OFF_MISC + 48);

    const int tid   = threadIdx.x;
    const int lane  = tid & 31;
    const int w     = tid >> 5;
    const int row0  = blockIdx.x * ROWS;
    const int batch = row0 >> 12;
    const int i0    = row0 & (NN - 1);
    const float* xb = x + (size_t)batch * NN * 3;

    int kk = (kptr != nullptr) ? *kptr : 20;
    kk = max(1, min(kk, 32));
    const float voff = -1.0f / (float)kk;

    // ---- staging: transpose 4 points (3 LDG.128) into SoA float4 rows ----
    {
        const float4* xb4 = reinterpret_cast<const float4*>(xb);
#pragma unroll
        for (int it = 0; it < 4; ++it) {
            int m = it * NT + tid;                 // quad index 0..1023
            float4 q0 = xb4[3 * m], q1 = xb4[3 * m + 1], q2 = xb4[3 * m + 2];
            xs4[m] = make_float4(q0.x, q0.w, q1.z, q2.y);
            ys4[m] = make_float4(q0.y, q1.x, q1.w, q2.z);
            zs4[m] = make_float4(q0.z, q1.y, q2.x, q2.w);
        }
    }
    if (tid < ROWS) { act[tid] = 1; cnt[tid] = 0; }
    __syncthreads();

    // ---- per-row packed constants -2*x_i (scalar reads from SoA) ----
    u64 PMX[ROWS], PMY[ROWS], PMZ[ROWS];
    {
        const float* xsf = reinterpret_cast<const float*>(xs4);
        const float* ysf = reinterpret_cast<const float*>(ys4);
        const float* zsf = reinterpret_cast<const float*>(zs4);
#pragma unroll
        for (int r = 0; r < ROWS; ++r) {
            int i = i0 + r;
            PMX[r] = splat2(-2.0f * xsf[i]);
            PMY[r] = splat2(-2.0f * ysf[i]);
            PMZ[r] = splat2(-2.0f * zsf[i]);
        }
    }

    // ---- zero-fill this CTA's 4 output rows (streaming) ----
    {
        const float4 z4 = make_float4(0.f, 0.f, 0.f, 0.f);
        float4* ob = reinterpret_cast<float4*>(out) + (size_t)row0 * (NN / 4);
#pragma unroll
        for (int it = 0; it < 16; ++it) __stcs(&ob[it * NT + tid], z4);
    }

    // ---- pass 1: 4 candidates/iter, packed math, per-thread minima ----
    float tm[ROWS];
#pragma unroll
    for (int r = 0; r < ROWS; ++r) tm[r] = 3.0e38f;
#pragma unroll
    for (int t = 0; t < 4; ++t) {
        int g = t * NT + tid;                     // float4-group; j = 4g..4g+3
        ulonglong2 X = xsu[g], Y = ysu[g], Z = zsu[g];
        u64 w01 = fma2(X.x, X.x, fma2(Y.x, Y.x, mul2(Z.x, Z.x)));
        u64 w23 = fma2(X.y, X.y, fma2(Y.y, Y.y, mul2(Z.y, Z.y)));
#pragma unroll
        for (int r = 0; r < ROWS; ++r) {
            u64 s01 = fma2(X.x, PMX[r], fma2(Y.x, PMY[r], fma2(Z.x, PMZ[r], w01)));
            u64 s23 = fma2(X.y, PMX[r], fma2(Y.y, PMY[r], fma2(Z.y, PMZ[r], w23)));
            float m4 = fminf(fminf(lo2(s01), hi2(s01)),
                             fminf(lo2(s23), hi2(s23)));
            tm[r] = fminf(tm[r], m4);
        }
    }
    // group-of-8 minima -> u16 ordered prefixes. Group a = tid>>3 covers
    // threads [8a,8a+8) x 4 t-iters x 4 cands = 128 disjoint candidates.
#pragma unroll
    for (int r = 0; r < ROWS; ++r) {
        float v = tm[r];
        v = fminf(v, __shfl_down_sync(0xFFFFFFFFu, v, 4, 8));
        v = fminf(v, __shfl_down_sync(0xFFFFFFFFu, v, 2, 8));
        v = fminf(v, __shfl_down_sync(0xFFFFFFFFu, v, 1, 8));
        if ((tid & 7) == 0)
            tm16[r][tid >> 3] = (unsigned short)(f2ord(v) >> 16);
    }
    __syncthreads();

    // ---- threshold: warp r<4 counting-ranks the 32 group minima ----
    unsigned T16base = 0;
    if (w < ROWS) {
        const unsigned lm = (unsigned)tm16[w][lane];
        int c = 0;
#pragma unroll
        for (int s = 0; s < 32; ++s) {
            unsigned v = __shfl_sync(0xFFFFFFFFu, lm, s);
            c += (v < lm || (v == lm && s < lane)) ? 1 : 0;
        }
        unsigned eq = __ballot_sync(0xFFFFFFFFu, c == kk - 1);
        T16base = __shfl_sync(0xFFFFFFFFu, lm, __ffs(eq) - 1);
        if (lane == 0) sT16[w] = T16base;
        knn[w][lane] = -1;                 // init for pass4
    }
    __syncthreads();

    // ---- fast collection (attempt 0): straight-line, fully unrolled ----
    {
        float thrf[ROWS];
#pragma unroll
        for (int r = 0; r < ROWS; ++r)
            thrf[r] = ord2f((sT16[r] << 16) | 0xFFFFu);

#pragma unroll
        for (int t = 0; t < 4; ++t) {
            int g = t * NT + tid;
            ulonglong2 X = xsu[g], Y = ysu[g], Z = zsu[g];
            u64 w01 = fma2(X.x, X.x, fma2(Y.x, Y.x, mul2(Z.x, Z.x)));
            u64 w23 = fma2(X.y, X.y, fma2(Y.y, Y.y, mul2(Z.y, Z.y)));
            int j0 = 4 * g;
#pragma unroll
            for (int r = 0; r < ROWS; ++r) {
                u64 s01 = fma2(X.x, PMX[r], fma2(Y.x, PMY[r], fma2(Z.x, PMZ[r], w01)));
                u64 s23 = fma2(X.y, PMX[r], fma2(Y.y, PMY[r], fma2(Z.y, PMZ[r], w23)));
                float s0 = lo2(s01), s1 = hi2(s01);
                float s2 = lo2(s23), s3 = hi2(s23);
                float hm = fminf(fminf(s0, s1), fminf(s2, s3));
                if (__any_sync(0xFFFFFFFFu, hm <= thrf[r])) {
                    if (s0 <= thrf[r]) {
                        int pos = atomicAdd(&cnt[r], 1);
                        if (pos < CAP)
                            cand[r][pos] = ((u64)f2ord(s0) << 32) | (unsigned)j0;
                    }
                    if (s1 <= thrf[r]) {
                        int pos = atomicAdd(&cnt[r], 1);
                        if (pos < CAP)
                            cand[r][pos] = ((u64)f2ord(s1) << 32) | (unsigned)(j0 + 1);
                    }
                    if (s2 <= thrf[r]) {
                        int pos = atomicAdd(&cnt[r], 1);
                        if (pos < CAP)
                            cand[r][pos] = ((u64)f2ord(s2) << 32) | (unsigned)(j0 + 2);
                    }
                    if (s3 <= thrf[r]) {
                        int pos = atomicAdd(&cnt[r], 1);
                        if (pos < CAP)
                            cand[r][pos] = ((u64)f2ord(s3) << 32) | (unsigned)(j0 + 3);
                    }
                }
            }
        }
    }
    __syncthreads();
    if (tid < ROWS) act[tid] = (cnt[tid] > CAP) ? 1 : 0;
    if (tid == 0) *anyf = 0;
    __syncthreads();
    if (tid < ROWS && act[tid]) atomicOr(anyf, 1);
    __syncthreads();

    // ---- retry fallback (statistically unreachable; uniform branch) ----
    if (__builtin_expect(*anyf, 0)) {
        for (int attempt = 1; attempt < 3; ++attempt) {
            if (w < ROWS && lane == 0 && act[w]) {
                unsigned d = (unsigned)attempt;
                sT16[w] = (T16base > d) ? (T16base - d) : 0u;
                cnt[w] = 0;
            }
            __syncthreads();
            float thrf[ROWS];
#pragma unroll
            for (int r = 0; r < ROWS; ++r)
                thrf[r] = act[r] ? ord2f((sT16[r] << 16) | 0xFFFFu)
                                 : __int_as_float(0xFF800000);   // -inf
#pragma unroll 1
            for (int t = 0; t < 4; ++t) {
                int g = t * NT + tid;
                ulonglong2 X = xsu[g], Y = ysu[g], Z = zsu[g];
                u64 w01 = fma2(X.x, X.x, fma2(Y.x, Y.x, mul2(Z.x, Z.x)));
                u64 w23 = fma2(X.y, X.y, fma2(Y.y, Y.y, mul2(Z.y, Z.y)));
                int j0 = 4 * g;
#pragma unroll
                for (int r = 0; r < ROWS; ++r) {
                    u64 s01 = fma2(X.x, PMX[r], fma2(Y.x, PMY[r], fma2(Z.x, PMZ[r], w01)));
                    u64 s23 = fma2(X.y, PMX[r], fma2(Y.y, PMY[r], fma2(Z.y, PMZ[r], w23)));
                    float sv[4] = {lo2(s01), hi2(s01), lo2(s23), hi2(s23)};
#pragma unroll
                    for (int q = 0; q < 4; ++q) {
                        if (sv[q] <= thrf[r]) {
                            int pos = atomicAdd(&cnt[r], 1);
                            if (pos < CAP)
                                cand[r][pos] =
                                    ((u64)f2ord(sv[q]) << 32) | (unsigned)(j0 + q);
                        }
                    }
                }
            }
            __syncthreads();
            if (tid < ROWS) {
                if (act[tid]) act[tid] = (cnt[tid] > CAP) ? 1 : 0;
            }
            if (tid == 0) {
                int a = 0;
#pragma unroll
                for (int r = 0; r < ROWS; ++r) a |= act[r];
                *anyf = a;
            }
            __syncthreads();
            if (!*anyf) break;
        }
    }

    // ---- pass 4: warps w and w+4 co-rank row (w & 3); one key per lane ----
    {
        const int r = w & 3;
        const int c = min(cnt[r], CAP);
        const int slot = lane + ((w >> 2) << 5);   // w<4: 0..31, w>=4: 32..63
        u64 my = (slot < c) ? cand[r][slot] : ~0ull;
        int rk = 0;
#pragma unroll 4
        for (int s = 0; s < c; ++s)
            rk += (cand[r][s] < my) ? 1 : 0;       // LDS broadcast
        if (my != ~0ull && rk < kk)
            knn[r][rk] = (int)(unsigned)my;
    }
    __syncthreads();

    // ---- scatter: warp r<4 writes its row's nonzeros + diagonal ----
    if (w < ROWS) {
        const int r = w;
        const int grow = row0 + r;
        const int iloc = i0 + r;
        float* orf = out + (size_t)grow * NN;
        int j = (lane < kk) ? knn[r][lane] : -1;
        bool selfin = (j == iloc);
        unsigned fmask = __ballot_sync(0xFFFFFFFFu, selfin);
        if (lane < kk && j >= 0)
            orf[j] = selfin ? (1.0f + voff) : voff;
        if (lane == 0 && fmask == 0u)
            orf[iloc] = 1.0f;
    }
}

extern "C" void kernel_launch(void* const* d_in, const int* in_sizes, int n_in,
                              void* d_out, int out_size) {
    const float* x   = (const float*)d_in[0];
    const int*   kpt = (n_in >= 2) ? (const int*)d_in[1] : nullptr;
    float*       out = (float*)d_out;

    int total_rows = in_sizes[0] / 3;      // 16384
    int grid = total_rows / ROWS;          // 4096

    cudaFuncSetAttribute(gcn_fused,
                         cudaFuncAttributeMaxDynamicSharedMemorySize, SMEM_TOTAL);
    gcn_fused<<<grid, NT, SMEM_TOTAL>>>(x, kpt, out);
}

// round 8
// speedup vs baseline: 1.2021x; 1.2021x over previous
#include <cuda_runtime.h>
#include <cstdint>

// ---------------------------------------------------------------------------
// BaseGCN: kNN + Laplacian, two kernels.
//   gcn_prep : transpose x into SoA scratch g_soa[batch][{x,y,z,w=|x|^2}][4096]
//   gcn_main : one CTA = 4 rows; candidates read via LDG.128 from g_soa
//              (L2/L1-resident, 64KB/batch shared by 1024 CTAs); no point
//              tile in smem -> smem ~2.9KB, launch_bounds(256,5) -> 40 warps.
// out[g,i,j] = (j==i) - (1/k) * [j in knn(i)]   (deg == k always).
//
//  pass1: packed f32x2 distances (w preloaded); per-thread minima for 4 rows
//         -> 32 group-of-8 minima (u16 ordered prefixes)
//  thr:   warp r<4 counting-ranks the 32 minima; rank k-1 value T guarantees
//         >= k candidates <= T  =>  collected set contains the exact top-k
//  collect: recompute s, vote-gated gather of (ord(s),j) keys <= T (~23)
//  pass4: warps w / w+4 co-rank row (w&3) -> exact top-k (64-bit keys =>
//         lowest-index tie-break, matching lax.top_k)
//  write: rows zeroed early (__stcs, drains under compute); scatter at end
// ---------------------------------------------------------------------------

constexpr int NN   = 4096;
constexpr int ROWS = 4;
constexpr int NT   = 256;
constexpr int CAP  = 64;

__device__ float g_soa[4 * 4 * NN];     // 256 KB scratch

using u64 = unsigned long long;

__device__ __forceinline__ u64 fma2(u64 a, u64 b, u64 c) {
    u64 d; asm("fma.rn.f32x2 %0, %1, %2, %3;" : "=l"(d) : "l"(a), "l"(b), "l"(c));
    return d;
}
__device__ __forceinline__ u64 pack2(float a, float b) {
    u64 d; asm("mov.b64 %0, {%1, %2};" : "=l"(d) : "f"(a), "f"(b));
    return d;
}
__device__ __forceinline__ u64 splat2(float a) { return pack2(a, a); }
__device__ __forceinline__ float lo2(u64 v) { return __uint_as_float((unsigned)v); }
__device__ __forceinline__ float hi2(u64 v) { return __uint_as_float((unsigned)(v >> 32)); }

__device__ __forceinline__ unsigned f2ord(float f) {
    unsigned b = __float_as_uint(f);
    return b ^ ((b & 0x80000000u) ? 0xFFFFFFFFu : 0x80000000u);
}
__device__ __forceinline__ float ord2f(unsigned u) {
    unsigned b = (u & 0x80000000u) ? (u ^ 0x80000000u) : ~u;
    return __uint_as_float(b);
}

// ====================== prologue: AoS -> SoA + |x|^2 =======================
extern "C" __global__ void __launch_bounds__(NT)
gcn_prep(const float* __restrict__ x, int total) {
    int p = blockIdx.x * NT + threadIdx.x;
    if (p < total) {
        float a = x[3 * p], b = x[3 * p + 1], c = x[3 * p + 2];
        int batch = p >> 12, i = p & (NN - 1);
        float* base = g_soa + (size_t)batch * 4 * NN;
        base[i]          = a;
        base[NN + i]     = b;
        base[2 * NN + i] = c;
        base[3 * NN + i] = fmaf(a, a, fmaf(b, b, c * c));
    }
}

// ============================== main kernel ================================
extern "C" __global__ void __launch_bounds__(NT, 5)
gcn_main(const int* __restrict__ kptr, float* __restrict__ out) {
    __shared__ unsigned short tm16[ROWS][32];
    __shared__ u64 cand[ROWS][CAP];
    __shared__ int knn[ROWS][32];
    __shared__ unsigned sT16[ROWS];
    __shared__ int cnt[ROWS];
    __shared__ int act[ROWS];
    __shared__ int anyf;

    const int tid   = threadIdx.x;
    const int lane  = tid & 31;
    const int w     = tid >> 5;
    const int row0  = blockIdx.x * ROWS;
    const int batch = row0 >> 12;
    const int i0    = row0 & (NN - 1);

    int kk = (kptr != nullptr) ? *kptr : 20;
    kk = max(1, min(kk, 32));
    const float voff = -1.0f / (float)kk;

    const float* bb = g_soa + (size_t)batch * 4 * NN;
    const ulonglong2* bu = reinterpret_cast<const ulonglong2*>(bb);
    // X at bu[g], Y at bu[g+1024], Z at bu[g+2048], W at bu[g+3072]

    // ---- per-row packed constants -2*x_i ----
    u64 PMX[ROWS], PMY[ROWS], PMZ[ROWS];
#pragma unroll
    for (int r = 0; r < ROWS; ++r) {
        int i = i0 + r;
        PMX[r] = splat2(-2.0f * __ldg(&bb[i]));
        PMY[r] = splat2(-2.0f * __ldg(&bb[NN + i]));
        PMZ[r] = splat2(-2.0f * __ldg(&bb[2 * NN + i]));
    }
    if (tid < ROWS) cnt[tid] = 0;

    // ---- zero-fill this CTA's 4 output rows (streaming, drains under compute)
    {
        const float4 z4 = make_float4(0.f, 0.f, 0.f, 0.f);
        float4* ob = reinterpret_cast<float4*>(out) + (size_t)row0 * (NN / 4);
#pragma unroll
        for (int it = 0; it < 16; ++it) __stcs(&ob[it * NT + tid], z4);
    }

    // ---- pass 1: 4 candidates/iter via LDG.128, packed minima ----
    float tm[ROWS];
#pragma unroll
    for (int r = 0; r < ROWS; ++r) tm[r] = 3.0e38f;
#pragma unroll 2
    for (int t = 0; t < 4; ++t) {
        int g = t * NT + tid;                 // float4-group; j = 4g..4g+3
        ulonglong2 X = __ldg(&bu[g]);
        ulonglong2 Y = __ldg(&bu[g + 1024]);
        ulonglong2 Z = __ldg(&bu[g + 2048]);
        ulonglong2 W = __ldg(&bu[g + 3072]);
#pragma unroll
        for (int r = 0; r < ROWS; ++r) {
            u64 s01 = fma2(X.x, PMX[r], fma2(Y.x, PMY[r], fma2(Z.x, PMZ[r], W.x)));
            u64 s23 = fma2(X.y, PMX[r], fma2(Y.y, PMY[r], fma2(Z.y, PMZ[r], W.y)));
            float m4 = fminf(fminf(lo2(s01), hi2(s01)),
                             fminf(lo2(s23), hi2(s23)));
            tm[r] = fminf(tm[r], m4);
        }
    }
    // group-of-8 minima -> u16 ordered prefixes. Group a = tid>>3 covers
    // threads [8a,8a+8) x 4 t-iters x 4 cands = 128 disjoint candidates.
#pragma unroll
    for (int r = 0; r < ROWS; ++r) {
        float v = tm[r];
        v = fminf(v, __shfl_down_sync(0xFFFFFFFFu, v, 4, 8));
        v = fminf(v, __shfl_down_sync(0xFFFFFFFFu, v, 2, 8));
        v = fminf(v, __shfl_down_sync(0xFFFFFFFFu, v, 1, 8));
        if ((tid & 7) == 0)
            tm16[r][tid >> 3] = (unsigned short)(f2ord(v) >> 16);
    }
    __syncthreads();

    // ---- threshold: warp r<4 counting-ranks the 32 group minima ----
    unsigned T16base = 0;
    if (w < ROWS) {
        const unsigned lm = (unsigned)tm16[w][lane];
        int c = 0;
#pragma unroll
        for (int s = 0; s < 32; ++s) {
            unsigned v = __shfl_sync(0xFFFFFFFFu, lm, s);
            c += (v < lm || (v == lm && s < lane)) ? 1 : 0;
        }
        unsigned eq = __ballot_sync(0xFFFFFFFFu, c == kk - 1);
        T16base = __shfl_sync(0xFFFFFFFFu, lm, __ffs(eq) - 1);
        if (lane == 0) sT16[w] = T16base;
        knn[w][lane] = -1;                    // init for pass4
    }
    __syncthreads();

    // ---- fast collection (attempt 0) ----
    {
        float thrf[ROWS];
#pragma unroll
        for (int r = 0; r < ROWS; ++r)
            thrf[r] = ord2f((sT16[r] << 16) | 0xFFFFu);

#pragma unroll 2
        for (int t = 0; t < 4; ++t) {
            int g = t * NT + tid;
            ulonglong2 X = __ldg(&bu[g]);
            ulonglong2 Y = __ldg(&bu[g + 1024]);
            ulonglong2 Z = __ldg(&bu[g + 2048]);
            ulonglong2 W = __ldg(&bu[g + 3072]);
            int j0 = 4 * g;
#pragma unroll
            for (int r = 0; r < ROWS; ++r) {
                u64 s01 = fma2(X.x, PMX[r], fma2(Y.x, PMY[r], fma2(Z.x, PMZ[r], W.x)));
                u64 s23 = fma2(X.y, PMX[r], fma2(Y.y, PMY[r], fma2(Z.y, PMZ[r], W.y)));
                float s0 = lo2(s01), s1 = hi2(s01);
                float s2 = lo2(s23), s3 = hi2(s23);
                float hm = fminf(fminf(s0, s1), fminf(s2, s3));
                if (__any_sync(0xFFFFFFFFu, hm <= thrf[r])) {
                    if (s0 <= thrf[r]) {
                        int pos = atomicAdd(&cnt[r], 1);
                        if (pos < CAP)
                            cand[r][pos] = ((u64)f2ord(s0) << 32) | (unsigned)j0;
                    }
                    if (s1 <= thrf[r]) {
                        int pos = atomicAdd(&cnt[r], 1);
                        if (pos < CAP)
                            cand[r][pos] = ((u64)f2ord(s1) << 32) | (unsigned)(j0 + 1);
                    }
                    if (s2 <= thrf[r]) {
                        int pos = atomicAdd(&cnt[r], 1);
                        if (pos < CAP)
                            cand[r][pos] = ((u64)f2ord(s2) << 32) | (unsigned)(j0 + 2);
                    }
                    if (s3 <= thrf[r]) {
                        int pos = atomicAdd(&cnt[r], 1);
                        if (pos < CAP)
                            cand[r][pos] = ((u64)f2ord(s3) << 32) | (unsigned)(j0 + 3);
                    }
                }
            }
        }
    }
    __syncthreads();

    // ---- overflow check: broadcast reads, uniform branch (no extra sync) ----
    bool ovf = (cnt[0] > CAP) | (cnt[1] > CAP) | (cnt[2] > CAP) | (cnt[3] > CAP);

    // ---- retry fallback (statistically unreachable) ----
    if (__builtin_expect(ovf, 0)) {
        if (tid < ROWS) act[tid] = (cnt[tid] > CAP) ? 1 : 0;
        __syncthreads();
        for (int attempt = 1; attempt < 3; ++attempt) {
            if (w < ROWS && lane == 0 && act[w]) {
                unsigned d = (unsigned)attempt;
                sT16[w] = (T16base > d) ? (T16base - d) : 0u;
                cnt[w] = 0;
            }
            __syncthreads();
            float thrf[ROWS];
#pragma unroll
            for (int r = 0; r < ROWS; ++r)
                thrf[r] = act[r] ? ord2f((sT16[r] << 16) | 0xFFFFu)
                                 : __int_as_float(0xFF800000);   // -inf
#pragma unroll 1
            for (int t = 0; t < 4; ++t) {
                int g = t * NT + tid;
                ulonglong2 X = __ldg(&bu[g]);
                ulonglong2 Y = __ldg(&bu[g + 1024]);
                ulonglong2 Z = __ldg(&bu[g + 2048]);
                ulonglong2 W = __ldg(&bu[g + 3072]);
                int j0 = 4 * g;
#pragma unroll
                for (int r = 0; r < ROWS; ++r) {
                    u64 s01 = fma2(X.x, PMX[r], fma2(Y.x, PMY[r], fma2(Z.x, PMZ[r], W.x)));
                    u64 s23 = fma2(X.y, PMX[r], fma2(Y.y, PMY[r], fma2(Z.y, PMZ[r], W.y)));
                    float sv[4] = {lo2(s01), hi2(s01), lo2(s23), hi2(s23)};
#pragma unroll
                    for (int q = 0; q < 4; ++q) {
                        if (sv[q] <= thrf[r]) {
                            int pos = atomicAdd(&cnt[r], 1);
                            if (pos < CAP)
                                cand[r][pos] =
                                    ((u64)f2ord(sv[q]) << 32) | (unsigned)(j0 + q);
                        }
                    }
                }
            }
            __syncthreads();
            if (tid < ROWS) {
                if (act[tid]) act[tid] = (cnt[tid] > CAP) ? 1 : 0;
            }
            if (tid == 0) {
                int a = 0;
#pragma unroll
                for (int r = 0; r < ROWS; ++r) a |= act[r];
                anyf = a;
            }
            __syncthreads();
            if (!anyf) break;
        }
    }

    // ---- pass 4: warps w and w+4 co-rank row (w & 3); one key per lane ----
    {
        const int r = w & 3;
        const int c = min(cnt[r], CAP);
        const int slot = lane + ((w >> 2) << 5);   // w<4: 0..31, w>=4: 32..63
        u64 my = (slot < c) ? cand[r][slot] : ~0ull;
        int rk = 0;
#pragma unroll 4
        for (int s = 0; s < c; ++s)
            rk += (cand[r][s] < my) ? 1 : 0;       // LDS broadcast
        if (my != ~0ull && rk < kk)
            knn[r][rk] = (int)(unsigned)my;
    }
    __syncthreads();

    // ---- scatter: warp r<4 writes its row's nonzeros + diagonal ----
    if (w < ROWS) {
        const int r = w;
        const int grow = row0 + r;
        const int iloc = i0 + r;
        float* orf = out + (size_t)grow * NN;
        int j = (lane < kk) ? knn[r][lane] : -1;
        bool selfin = (j == iloc);
        unsigned fmask = __ballot_sync(0xFFFFFFFFu, selfin);
        if (lane < kk && j >= 0)
            orf[j] = selfin ? (1.0f + voff) : voff;
        if (lane == 0 && fmask == 0u)
            orf[iloc] = 1.0f;
    }
}

// ================================ launch ===================================
extern "C" void kernel_launch(void* const* d_in, const int* in_sizes, int n_in,
                              void* d_out, int out_size) {
    const float* x   = (const float*)d_in[0];
    const int*   kpt = (n_in >= 2) ? (const int*)d_in[1] : nullptr;
    float*       out = (float*)d_out;

    int total_pts = in_sizes[0] / 3;       // 16384
    int gridP = (total_pts + NT - 1) / NT; // 64
    int gridM = total_pts / ROWS;          // 4096

    gcn_prep<<<gridP, NT>>>(x, total_pts);
    gcn_main<<<gridM, NT>>>(kpt, out);
}